// round 15
// baseline (speedup 1.0000x reference)
#include <cuda_runtime.h>
#include <cuda_fp16.h>
#include <cstdint>

#define BATCH 512
#define INC   1152
#define NC    10
#define DC    16
#define JD    160      // NC*DC
#define NSLOT 80       // half2 slots per (b,i): slot m holds jd {2m, 2m+1}
#define CSZ   6        // cluster CTAs per batch
#define IQ    192      // i-range per route CTA (INC / CSZ)
#define IQH   96       // TMA chunk split
#define RW    10       // warps per route CTA (320 threads)
#define RTHR  320
#define EPSQ  1e-7f
#define UBYTES (IQ * NSLOT * 4)    // 61440 B per CTA slice
#define CHBYTES (IQH * NSLOT * 4)  // 30720 B per TMA chunk

typedef unsigned long long u64;

// u_hat in fp16, layout [b][i][slot], slot m = jd pair (2m, 2m+1). 188 MB.
__device__ __half2 g_uhat[(size_t)BATCH * INC * NSLOT];

// ---------------------------------------------------------------------------
// helpers
// ---------------------------------------------------------------------------
__device__ __forceinline__ void cluster_sync() {
    asm volatile("barrier.cluster.arrive.aligned;\n\t"
                 "barrier.cluster.wait.aligned;" ::: "memory");
}

__device__ __forceinline__ float peer_f32(const float* p, unsigned int peer) {
    unsigned int a = (unsigned int)__cvta_generic_to_shared(p);
    unsigned int r;
    asm("mapa.shared::cluster.u32 %0, %1, %2;" : "=r"(r) : "r"(a), "r"(peer));
    float v;
    asm volatile("ld.shared::cluster.f32 %0, [%1];" : "=f"(v) : "r"(r));
    return v;
}

__device__ __forceinline__ u64 pack2(float lo, float hi) {
    u64 r;
    asm("mov.b64 %0, {%1, %2};" : "=l"(r) : "f"(lo), "f"(hi));
    return r;
}
__device__ __forceinline__ void fma2(u64& d, u64 a, u64 b) {
    asm("fma.rn.f32x2 %0, %1, %2, %3;" : "=l"(d) : "l"(a), "l"(b), "l"(d));
}
__device__ __forceinline__ void add2(u64& d, u64 a) {
    asm("add.rn.f32x2 %0, %0, %1;" : "+l"(d) : "l"(a));
}
// f32x2 {lo,hi} -> half2 {.x=lo, .y=hi}
__device__ __forceinline__ __half2 f2_to_h2(u64 v) {
    float lo, hi;
    asm("mov.b64 {%0, %1}, %2;" : "=f"(lo), "=f"(hi) : "l"(v));
    unsigned int r;
    asm("cvt.rn.f16x2.f32 %0, %1, %2;" : "=r"(r) : "f"(hi), "f"(lo));
    return *(__half2*)&r;
}
union F2U { float2 f; u64 u; };

__device__ __forceinline__ u64 h2_to_u64f2(__half2 h) {
    F2U t;
    t.f = __half22float2(h);
    return t.u;
}

__device__ __forceinline__ void mbar_wait0(unsigned int addr) {
    unsigned int done;
    asm volatile(
        "{\n\t.reg .pred p;\n\t"
        "mbarrier.try_wait.parity.acquire.cta.shared::cta.b64 p, [%1], %2;\n\t"
        "selp.b32 %0, 1, 0, p;\n\t}"
        : "=r"(done) : "r"(addr), "r"(0u) : "memory");
    while (!done) {
        asm volatile(
            "{\n\t.reg .pred p;\n\t"
            "mbarrier.try_wait.parity.acquire.cta.shared::cta.b64 p, [%1], %2, 0x989680;\n\t"
            "selp.b32 %0, 1, 0, p;\n\t}"
            : "=r"(done) : "r"(addr), "r"(0u) : "memory");
    }
}

// ---------------------------------------------------------------------------
// Kernel A: u_hat[b,i,jd] = sum_k inputs[b,i,k] * W[jd(i),k], fp16 output.
// R10 exact (48 us): one CTA per i; float4 inputs staged in smem; main loop
// is broadcast LDS.128 x2 + in-loop packs + FFMA2 + STG, unroll 2.
// ---------------------------------------------------------------------------
__global__ __launch_bounds__(256) void uhat_kernel(const float* __restrict__ inp,
                                                   const float* __restrict__ W) {
    __shared__ float4 sin[BATCH][2];   // 16 KB: inputs[b][i][0..7]

    const int tid = threadIdx.x;
    const int warp = tid >> 5;
    const int lane = tid & 31;
    const int i = blockIdx.x;

    // ---- stage inputs: thread t loads b = t, t+256 (2x2 LDG.128, MLP 4) ----
    {
        const float4* p0 = (const float4*)(inp + ((size_t)tid * INC + i) * 8);
        const float4* p1 =
            (const float4*)(inp + ((size_t)(tid + 256) * INC + i) * 8);
        float4 a0 = __ldg(p0), a1 = __ldg(p0 + 1);
        float4 b0 = __ldg(p1), b1 = __ldg(p1 + 1);
        sin[tid][0] = a0;
        sin[tid][1] = a1;
        sin[tid + 256][0] = b0;
        sin[tid + 256][1] = b1;
    }

    // ---- W pairs packed as f32x2 in registers ----
    u64 wpA[8], wpB[8], wpC[8];
#define LOADW(dst, jd0)                                                        \
    {                                                                          \
        const int j_ = (jd0) >> 4, d_ = (jd0) & 15;                            \
        const float4* p_ =                                                     \
            (const float4*)(W + (((size_t)j_ * INC + i) * DC + d_) * 8);       \
        float4 q0 = __ldg(p_), q1 = __ldg(p_ + 1), q2 = __ldg(p_ + 2),         \
               q3 = __ldg(p_ + 3);                                             \
        dst[0] = pack2(q0.x, q2.x); dst[1] = pack2(q0.y, q2.y);                \
        dst[2] = pack2(q0.z, q2.z); dst[3] = pack2(q0.w, q2.w);                \
        dst[4] = pack2(q1.x, q3.x); dst[5] = pack2(q1.y, q3.y);                \
        dst[6] = pack2(q1.z, q3.z); dst[7] = pack2(q1.w, q3.w);                \
    }
    LOADW(wpA, 2 * lane);
    LOADW(wpB, 64 + 2 * lane);
    if (lane < 16) {
        LOADW(wpC, 128 + 2 * lane);
    } else {
#pragma unroll
        for (int k = 0; k < 8; k++) wpC[k] = 0ull;
    }
#undef LOADW

    __syncthreads();

    // ---- main loop: warp owns 64 batches; inputs via broadcast LDS ----
    const int b0 = warp * 64;
#pragma unroll 2
    for (int bb = 0; bb < 64; bb++) {
        const int b = b0 + bb;
        float4 x = sin[b][0], y = sin[b][1];

        u64 in2[8];
        in2[0] = pack2(x.x, x.x); in2[1] = pack2(x.y, x.y);
        in2[2] = pack2(x.z, x.z); in2[3] = pack2(x.w, x.w);
        in2[4] = pack2(y.x, y.x); in2[5] = pack2(y.y, y.y);
        in2[6] = pack2(y.z, y.z); in2[7] = pack2(y.w, y.w);

        u64 aA = 0ull, aB = 0ull, aC = 0ull;
#pragma unroll
        for (int k = 0; k < 8; k++) {
            fma2(aA, in2[k], wpA[k]);
            fma2(aB, in2[k], wpB[k]);
            fma2(aC, in2[k], wpC[k]);
        }
        __half2* up = g_uhat + ((size_t)b * INC + i) * NSLOT;
        up[lane] = f2_to_h2(aA);
        up[32 + lane] = f2_to_h2(aB);
        if (lane < 16) up[64 + lane] = f2_to_h2(aC);
    }
}

// ---------------------------------------------------------------------------
// Kernel R: routing. Cluster of 6 CTAs per batch (IQ=192, 320 threads,
// ~73 KB smem -> 3 CTAs/SM). 2-chunk cp.async.bulk overlapped with pass-0.
// Per pass (fused A'+C):
//   A': lane=(io*16+j) computes fp16 dot t[i,j] for i=g*2+io, e=exp(t),
//       per-i softmax via intra-16-lane shfl sum, stores c=e/sum (fp16).
//   C : lane l<20 accumulates s += c[i,jC] * u[i,slot], broadcast loads.
// Then slim epilogue (double-buffered sfin, one cluster_sync per pass,
// shuffle squash, V in registers).
// ---------------------------------------------------------------------------
__global__ __launch_bounds__(RTHR, 3) __cluster_dims__(CSZ, 1, 1)
void route_kernel(float* __restrict__ out) {
    extern __shared__ char smraw[];
    __half2* Usm = (__half2*)smraw;                            // 61440 B
    float* red = (float*)(smraw + UBYTES);                     // RW*160 f
    float* sf0 = red + RW * JD;                                // 160 (DSMEM)
    float* sf1 = sf0 + JD;                                     // 160 (DSMEM)
    __half2* Vh2 = (__half2*)(sf1 + JD);                       // 80 half2
    __half* ch = (__half*)(Vh2 + NSLOT);                       // IQ*10 half
    u64* mbar = (u64*)(ch + IQ * NC);                          // 2 mbarriers

    const int tid = threadIdx.x;
    const int warp = tid >> 5;
    const int lane = tid & 31;
    const int b = blockIdx.x / CSZ;
    const unsigned int rank = blockIdx.x % CSZ;
    const bool act = (lane < 20);
    const int sl = act ? 4 * lane : 0;
    float2* red2 = (float2*)red;
    const unsigned int mbar_a = (unsigned int)__cvta_generic_to_shared(mbar);
    const unsigned int usm_a = (unsigned int)__cvta_generic_to_shared(Usm);

    float Vreg = 0.f;  // running V for this thread's jd (tid < 160)

    // ---- 2-chunk bulk async copy: g_uhat slice -> smem ----
    if (tid == 0) {
        asm volatile("mbarrier.init.shared.b64 [%0], %1;" ::"r"(mbar_a),
                     "r"(1u) : "memory");
        asm volatile("mbarrier.init.shared.b64 [%0], %1;" ::"r"(mbar_a + 8),
                     "r"(1u) : "memory");
    }
    __syncthreads();
    if (tid == 0) {
        const __half2* gsrc = g_uhat + ((size_t)b * INC + rank * IQ) * NSLOT;
#pragma unroll
        for (int c = 0; c < 2; c++) {
            asm volatile(
                "mbarrier.arrive.expect_tx.shared.b64 _, [%0], %1;"
                ::"r"(mbar_a + 8 * c), "r"((unsigned int)CHBYTES) : "memory");
            asm volatile(
                "cp.async.bulk.shared::cta.global.mbarrier::complete_tx::bytes "
                "[%0], [%1], %2, [%3];"
                ::"r"(usm_a + c * CHBYTES),
                "l"((const void*)(gsrc + (size_t)c * IQH * NSLOT)),
                "r"((unsigned int)CHBYTES), "r"(mbar_a + 8 * c) : "memory");
        }
    }

    // ---- pass-0 (c = 0.1 uniform): consume chunks as they arrive ----
    {
        u64 a0 = 0ull, a1 = 0ull, a2 = 0ull, a3 = 0ull;
        int i = warp;
        mbar_wait0(mbar_a);
        if (act) {
            for (; i < IQH; i += RW) {
                uint4 u = *(const uint4*)(Usm + (size_t)i * NSLOT + sl);
                add2(a0, h2_to_u64f2(*(__half2*)&u.x));
                add2(a1, h2_to_u64f2(*(__half2*)&u.y));
                add2(a2, h2_to_u64f2(*(__half2*)&u.z));
                add2(a3, h2_to_u64f2(*(__half2*)&u.w));
            }
        }
        mbar_wait0(mbar_a + 8);
        if (act) {
            for (; i < IQ; i += RW) {
                uint4 u = *(const uint4*)(Usm + (size_t)i * NSLOT + sl);
                add2(a0, h2_to_u64f2(*(__half2*)&u.x));
                add2(a1, h2_to_u64f2(*(__half2*)&u.y));
                add2(a2, h2_to_u64f2(*(__half2*)&u.z));
                add2(a3, h2_to_u64f2(*(__half2*)&u.w));
            }
            F2U t0, t1, t2, t3;
            t0.u = a0; t1.u = a1; t2.u = a2; t3.u = a3;
            red2[warp * 80 + sl + 0] = t0.f;
            red2[warp * 80 + sl + 1] = t1.f;
            red2[warp * 80 + sl + 2] = t2.f;
            red2[warp * 80 + sl + 3] = t3.f;
        }
    }

    // lane mapping for stage A': lane = io*16 + j, io in 0..1, j in 0..15
    const int ioA = lane >> 4;
    const int jA = lane & 15;
    const bool actA = (jA < NC);
    const int jC = lane >> 1;

    // ---- per-pass epilogue (p = 0,1,2), sfbuf double-buffered ----
#define EPILOGUE(P, SF)                                                        \
    __syncthreads();                                                           \
    if (tid < JD) {                                                            \
        float s_ = 0.f;                                                        \
        _Pragma("unroll") for (int w_ = 0; w_ < RW; w_++)                      \
            s_ += red[w_ * JD + tid];                                          \
        (SF)[tid] = s_;                                                        \
    }                                                                          \
    cluster_sync();                                                            \
    if (tid < JD) {                                                            \
        float s_ = (SF)[tid];                                                  \
        _Pragma("unroll") for (unsigned int r_ = 1; r_ < CSZ; r_++) {          \
            unsigned int pr_ = rank + r_;                                      \
            if (pr_ >= CSZ) pr_ -= CSZ;                                        \
            s_ += peer_f32((SF) + tid, pr_);                                   \
        }                                                                      \
        if ((P) == 0) s_ *= 0.1f;                                              \
        float sq_ = s_ * s_;                                                   \
        sq_ += __shfl_xor_sync(0xffffffffu, sq_, 1);                           \
        sq_ += __shfl_xor_sync(0xffffffffu, sq_, 2);                           \
        sq_ += __shfl_xor_sync(0xffffffffu, sq_, 4);                           \
        sq_ += __shfl_xor_sync(0xffffffffu, sq_, 8);                           \
        float scl_ = sq_ / ((1.0f + sq_) * sqrtf(sq_ + EPSQ));                 \
        float v_ = scl_ * s_;                                                  \
        if ((P) == 2) {                                                        \
            if (rank == 0) out[(size_t)b * JD + tid] = v_;                     \
        } else {                                                               \
            Vreg += v_;                                                        \
            float vp_ = __shfl_down_sync(0xffffffffu, Vreg, 1);                \
            if (!(tid & 1)) Vh2[tid >> 1] = __floats2half2_rn(Vreg, vp_);      \
        }                                                                      \
    }                                                                          \
    __syncthreads();

    EPILOGUE(0, sf0)

    // ---- passes 1,2 from smem ----
    for (int p = 1; p <= 2; p++) {
        // ===== Stage A': dot + exp + per-i softmax in 16-lane groups;
        //       stores c = e / sum_j e directly (fp16). No stage B. =====
        {
            uint4 vr0 = make_uint4(0, 0, 0, 0), vr1 = vr0;
            if (actA) {
                vr0 = *(const uint4*)(Vh2 + 8 * jA);
                vr1 = *(const uint4*)(Vh2 + 8 * jA + 4);
            }
            __half2 w0 = *(__half2*)&vr0.x, w1 = *(__half2*)&vr0.y;
            __half2 w2 = *(__half2*)&vr0.z, w3 = *(__half2*)&vr0.w;
            __half2 w4 = *(__half2*)&vr1.x, w5 = *(__half2*)&vr1.y;
            __half2 w6 = *(__half2*)&vr1.z, w7 = *(__half2*)&vr1.w;
#pragma unroll 2
            for (int g = warp; g < IQ / 2; g += RW) {
                const int i = g * 2 + ioA;
                float e = 0.f;
                if (actA) {
                    const __half2* up = Usm + (size_t)i * NSLOT + 8 * jA;
                    uint4 u0 = *(const uint4*)up;
                    uint4 u1 = *(const uint4*)(up + 4);
                    __half2 acc = __hmul2(*(__half2*)&u0.x, w0);
                    acc = __hfma2(*(__half2*)&u0.y, w1, acc);
                    acc = __hfma2(*(__half2*)&u0.z, w2, acc);
                    acc = __hfma2(*(__half2*)&u0.w, w3, acc);
                    acc = __hfma2(*(__half2*)&u1.x, w4, acc);
                    acc = __hfma2(*(__half2*)&u1.y, w5, acc);
                    acc = __hfma2(*(__half2*)&u1.z, w6, acc);
                    acc = __hfma2(*(__half2*)&u1.w, w7, acc);
                    float2 tf = __half22float2(acc);
                    e = __expf(tf.x + tf.y);  // |t| small: no max-sub
                }
                float sv = e;  // sum over the 16-lane group (j>=10 adds 0)
                sv += __shfl_xor_sync(0xffffffffu, sv, 1);
                sv += __shfl_xor_sync(0xffffffffu, sv, 2);
                sv += __shfl_xor_sync(0xffffffffu, sv, 4);
                sv += __shfl_xor_sync(0xffffffffu, sv, 8);
                if (actA) {
                    float c = e * __fdividef(1.f, sv);
                    ch[i * NC + jA] = __float2half_rn(c);
                }
            }
        }
        __syncthreads();

        // ===== Stage C: s += c[i,jC] * u[i,slot] (broadcast loads) =====
        u64 s0 = 0ull, s1 = 0ull, s2 = 0ull, s3 = 0ull;
#pragma unroll 4
        for (int i = warp; i < IQ; i += RW) {
            uint4 u = *(const uint4*)(Usm + (size_t)i * NSLOT + sl);
            float cf = __half2float(ch[i * NC + jC]);
            u64 cc = pack2(cf, cf);
            fma2(s0, h2_to_u64f2(*(__half2*)&u.x), cc);
            fma2(s1, h2_to_u64f2(*(__half2*)&u.y), cc);
            fma2(s2, h2_to_u64f2(*(__half2*)&u.z), cc);
            fma2(s3, h2_to_u64f2(*(__half2*)&u.w), cc);
        }
        if (act) {
            F2U t0, t1, t2, t3;
            t0.u = s0; t1.u = s1; t2.u = s2; t3.u = s3;
            red2[warp * 80 + sl + 0] = t0.f;
            red2[warp * 80 + sl + 1] = t1.f;
            red2[warp * 80 + sl + 2] = t2.f;
            red2[warp * 80 + sl + 3] = t3.f;
        }
        if (p == 1) {
            EPILOGUE(1, sf1)
        } else {
            EPILOGUE(2, sf0)
        }
    }

    cluster_sync();  // exit safety: peers may still read this CTA's sf0
}

// ---------------------------------------------------------------------------
extern "C" void kernel_launch(void* const* d_in, const int* in_sizes, int n_in,
                              void* d_out, int out_size) {
    const float* inputs = (const float*)d_in[0];  // [512, 1152, 8]
    const float* W = (const float*)d_in[1];       // [10, 1152, 16, 8]
    float* out = (float*)d_out;                   // [512, 10, 16]

    uhat_kernel<<<INC, 256>>>(inputs, W);

    const int smem = UBYTES + RW * JD * 4 + 2 * JD * 4 + NSLOT * 4 +
                     IQ * NC * 2 + 16;  // ~73 KB
    cudaFuncSetAttribute(route_kernel,
                         cudaFuncAttributeMaxDynamicSharedMemorySize, smem);
    route_kernel<<<BATCH * CSZ, RTHR, smem>>>(out);
}

// round 16
// speedup vs baseline: 1.1036x; 1.1036x over previous
#include <cuda_runtime.h>
#include <cuda_fp16.h>
#include <cstdint>

#define BATCH 512
#define INC   1152
#define NC    10
#define DC    16
#define JD    160      // NC*DC
#define NSLOT 80       // half2 slots per (b,i): slot m holds jd {2m, 2m+1}
#define CSZ   6        // cluster CTAs per batch
#define NCLUST 74      // persistent clusters
#define IQ    192      // i-range per route CTA (INC / CSZ)
#define IQH   96       // TMA chunk split
#define RW    10       // warps per route CTA (320 threads)
#define RTHR  320
#define EPSQ  1e-7f
#define UBYTES (IQ * NSLOT * 4)    // 61440 B per CTA slice
#define CHBYTES (IQH * NSLOT * 4)  // 30720 B per TMA chunk

typedef unsigned long long u64;

// u_hat in fp16, layout [b][i][slot], slot m = jd pair (2m, 2m+1). 188 MB.
__device__ __half2 g_uhat[(size_t)BATCH * INC * NSLOT];

// ---------------------------------------------------------------------------
// helpers
// ---------------------------------------------------------------------------
__device__ __forceinline__ void cluster_sync() {
    asm volatile("barrier.cluster.arrive.aligned;\n\t"
                 "barrier.cluster.wait.aligned;" ::: "memory");
}

__device__ __forceinline__ float peer_f32(const float* p, unsigned int peer) {
    unsigned int a = (unsigned int)__cvta_generic_to_shared(p);
    unsigned int r;
    asm("mapa.shared::cluster.u32 %0, %1, %2;" : "=r"(r) : "r"(a), "r"(peer));
    float v;
    asm volatile("ld.shared::cluster.f32 %0, [%1];" : "=f"(v) : "r"(r));
    return v;
}

__device__ __forceinline__ u64 pack2(float lo, float hi) {
    u64 r;
    asm("mov.b64 %0, {%1, %2};" : "=l"(r) : "f"(lo), "f"(hi));
    return r;
}
__device__ __forceinline__ void fma2(u64& d, u64 a, u64 b) {
    asm("fma.rn.f32x2 %0, %1, %2, %3;" : "=l"(d) : "l"(a), "l"(b), "l"(d));
}
__device__ __forceinline__ void add2(u64& d, u64 a) {
    asm("add.rn.f32x2 %0, %0, %1;" : "+l"(d) : "l"(a));
}
// f32x2 {lo,hi} -> half2 {.x=lo, .y=hi}
__device__ __forceinline__ __half2 f2_to_h2(u64 v) {
    float lo, hi;
    asm("mov.b64 {%0, %1}, %2;" : "=f"(lo), "=f"(hi) : "l"(v));
    unsigned int r;
    asm("cvt.rn.f16x2.f32 %0, %1, %2;" : "=r"(r) : "f"(hi), "f"(lo));
    return *(__half2*)&r;
}
union F2U { float2 f; u64 u; };

__device__ __forceinline__ u64 h2_to_u64f2(__half2 h) {
    F2U t;
    t.f = __half22float2(h);
    return t.u;
}

__device__ __forceinline__ void mbar_wait(unsigned int addr, unsigned int par) {
    unsigned int done;
    asm volatile(
        "{\n\t.reg .pred p;\n\t"
        "mbarrier.try_wait.parity.acquire.cta.shared::cta.b64 p, [%1], %2;\n\t"
        "selp.b32 %0, 1, 0, p;\n\t}"
        : "=r"(done) : "r"(addr), "r"(par) : "memory");
    while (!done) {
        asm volatile(
            "{\n\t.reg .pred p;\n\t"
            "mbarrier.try_wait.parity.acquire.cta.shared::cta.b64 p, [%1], %2, 0x989680;\n\t"
            "selp.b32 %0, 1, 0, p;\n\t}"
            : "=r"(done) : "r"(addr), "r"(par) : "memory");
    }
}

// issue 2-chunk bulk copy of batch bt's slice into Usm (tid 0 only)
__device__ __forceinline__ void issue_tma(int bt, unsigned int rank,
                                          unsigned int usm_a,
                                          unsigned int mbar_a) {
    const __half2* gsrc = g_uhat + ((size_t)bt * INC + rank * IQ) * NSLOT;
#pragma unroll
    for (int c = 0; c < 2; c++) {
        asm volatile(
            "mbarrier.arrive.expect_tx.shared.b64 _, [%0], %1;"
            ::"r"(mbar_a + 8 * c), "r"((unsigned int)CHBYTES) : "memory");
        asm volatile(
            "cp.async.bulk.shared::cta.global.mbarrier::complete_tx::bytes "
            "[%0], [%1], %2, [%3];"
            ::"r"(usm_a + c * CHBYTES),
            "l"((const void*)(gsrc + (size_t)c * IQH * NSLOT)),
            "r"((unsigned int)CHBYTES), "r"(mbar_a + 8 * c) : "memory");
    }
}

// ---------------------------------------------------------------------------
// Kernel A: u_hat[b,i,jd] = sum_k inputs[b,i,k] * W[jd(i),k], fp16 output.
// R10 exact (48 us): one CTA per i; float4 inputs staged in smem; main loop
// is broadcast LDS.128 x2 + in-loop packs + FFMA2 + STG, unroll 2.
// ---------------------------------------------------------------------------
__global__ __launch_bounds__(256) void uhat_kernel(const float* __restrict__ inp,
                                                   const float* __restrict__ W) {
    __shared__ float4 sin[BATCH][2];   // 16 KB: inputs[b][i][0..7]

    const int tid = threadIdx.x;
    const int warp = tid >> 5;
    const int lane = tid & 31;
    const int i = blockIdx.x;

    // ---- stage inputs: thread t loads b = t, t+256 (2x2 LDG.128, MLP 4) ----
    {
        const float4* p0 = (const float4*)(inp + ((size_t)tid * INC + i) * 8);
        const float4* p1 =
            (const float4*)(inp + ((size_t)(tid + 256) * INC + i) * 8);
        float4 a0 = __ldg(p0), a1 = __ldg(p0 + 1);
        float4 b0 = __ldg(p1), b1 = __ldg(p1 + 1);
        sin[tid][0] = a0;
        sin[tid][1] = a1;
        sin[tid + 256][0] = b0;
        sin[tid + 256][1] = b1;
    }

    // ---- W pairs packed as f32x2 in registers ----
    u64 wpA[8], wpB[8], wpC[8];
#define LOADW(dst, jd0)                                                        \
    {                                                                          \
        const int j_ = (jd0) >> 4, d_ = (jd0) & 15;                            \
        const float4* p_ =                                                     \
            (const float4*)(W + (((size_t)j_ * INC + i) * DC + d_) * 8);       \
        float4 q0 = __ldg(p_), q1 = __ldg(p_ + 1), q2 = __ldg(p_ + 2),         \
               q3 = __ldg(p_ + 3);                                             \
        dst[0] = pack2(q0.x, q2.x); dst[1] = pack2(q0.y, q2.y);                \
        dst[2] = pack2(q0.z, q2.z); dst[3] = pack2(q0.w, q2.w);                \
        dst[4] = pack2(q1.x, q3.x); dst[5] = pack2(q1.y, q3.y);                \
        dst[6] = pack2(q1.z, q3.z); dst[7] = pack2(q1.w, q3.w);                \
    }
    LOADW(wpA, 2 * lane);
    LOADW(wpB, 64 + 2 * lane);
    if (lane < 16) {
        LOADW(wpC, 128 + 2 * lane);
    } else {
#pragma unroll
        for (int k = 0; k < 8; k++) wpC[k] = 0ull;
    }
#undef LOADW

    __syncthreads();

    // ---- main loop: warp owns 64 batches; inputs via broadcast LDS ----
    const int b0 = warp * 64;
#pragma unroll 2
    for (int bb = 0; bb < 64; bb++) {
        const int b = b0 + bb;
        float4 x = sin[b][0], y = sin[b][1];

        u64 in2[8];
        in2[0] = pack2(x.x, x.x); in2[1] = pack2(x.y, x.y);
        in2[2] = pack2(x.z, x.z); in2[3] = pack2(x.w, x.w);
        in2[4] = pack2(y.x, y.x); in2[5] = pack2(y.y, y.y);
        in2[6] = pack2(y.z, y.z); in2[7] = pack2(y.w, y.w);

        u64 aA = 0ull, aB = 0ull, aC = 0ull;
#pragma unroll
        for (int k = 0; k < 8; k++) {
            fma2(aA, in2[k], wpA[k]);
            fma2(aB, in2[k], wpB[k]);
            fma2(aC, in2[k], wpC[k]);
        }
        __half2* up = g_uhat + ((size_t)b * INC + i) * NSLOT;
        up[lane] = f2_to_h2(aA);
        up[32 + lane] = f2_to_h2(aB);
        if (lane < 16) up[64 + lane] = f2_to_h2(aC);
    }
}

// ---------------------------------------------------------------------------
// Kernel R: PERSISTENT routing. 74 clusters of 6 CTAs; cluster c owns batches
// bt = c + 74*t. Stages per pass are R13/R14-exact (A: 3-i fp16 dot + exp;
// B: 1/sum; C: broadcast accumulate). Per-batch TMA is prefetched during the
// PREVIOUS batch's pass-2 epilogue (after the last Usm read); sfin start
// buffer alternates per batch so no end-of-batch cluster_sync is needed.
// ---------------------------------------------------------------------------
__global__ __launch_bounds__(RTHR, 3) __cluster_dims__(CSZ, 1, 1)
void route_kernel(float* __restrict__ out) {
    extern __shared__ char smraw[];
    __half2* Usm = (__half2*)smraw;                            // 61440 B
    float* red = (float*)(smraw + UBYTES);                     // RW*160 f
    float* sf0 = red + RW * JD;                                // 160 (DSMEM)
    float* sf1 = sf0 + JD;                                     // 160 (DSMEM)
    __half2* Vh2 = (__half2*)(sf1 + JD);                       // 80 half2
    __half* eh = (__half*)(Vh2 + NSLOT);                       // IQ*10 half
    float* wsm = (float*)(eh + IQ * NC);                       // IQ floats
    u64* mbar = (u64*)(wsm + IQ);                              // 2 mbarriers

    const int tid = threadIdx.x;
    const int warp = tid >> 5;
    const int lane = tid & 31;
    const int clust = blockIdx.x / CSZ;
    const unsigned int rank = blockIdx.x % CSZ;
    const bool act = (lane < 20);
    const int sl = act ? 4 * lane : 0;
    float2* red2 = (float2*)red;
    const unsigned int mbar_a = (unsigned int)__cvta_generic_to_shared(mbar);
    const unsigned int usm_a = (unsigned int)__cvta_generic_to_shared(Usm);

    // lane mappings
    const int ioA = lane / 10;
    const int jA = lane - 10 * ioA;
    const bool actA = (lane < 30);
    const int jC = lane >> 1;

    if (tid == 0) {
        asm volatile("mbarrier.init.shared.b64 [%0], %1;" ::"r"(mbar_a),
                     "r"(1u) : "memory");
        asm volatile("mbarrier.init.shared.b64 [%0], %1;" ::"r"(mbar_a + 8),
                     "r"(1u) : "memory");
    }
    __syncthreads();
    if (tid == 0) issue_tma(clust, rank, usm_a, mbar_a);

    // PRE: code injected after the first __syncthreads (all Usm reads done)
#define EPILOGUE(P, SF, PRE)                                                   \
    __syncthreads();                                                           \
    PRE                                                                        \
    if (tid < JD) {                                                            \
        float s_ = 0.f;                                                        \
        _Pragma("unroll") for (int w_ = 0; w_ < RW; w_++)                      \
            s_ += red[w_ * JD + tid];                                          \
        (SF)[tid] = s_;                                                        \
    }                                                                          \
    cluster_sync();                                                            \
    if (tid < JD) {                                                            \
        float s_ = (SF)[tid];                                                  \
        _Pragma("unroll") for (unsigned int r_ = 1; r_ < CSZ; r_++) {          \
            unsigned int pr_ = rank + r_;                                      \
            if (pr_ >= CSZ) pr_ -= CSZ;                                        \
            s_ += peer_f32((SF) + tid, pr_);                                   \
        }                                                                      \
        if ((P) == 0) s_ *= 0.1f;                                              \
        float sq_ = s_ * s_;                                                   \
        sq_ += __shfl_xor_sync(0xffffffffu, sq_, 1);                           \
        sq_ += __shfl_xor_sync(0xffffffffu, sq_, 2);                           \
        sq_ += __shfl_xor_sync(0xffffffffu, sq_, 4);                           \
        sq_ += __shfl_xor_sync(0xffffffffu, sq_, 8);                           \
        float scl_ = sq_ / ((1.0f + sq_) * sqrtf(sq_ + EPSQ));                 \
        float v_ = scl_ * s_;                                                  \
        if ((P) == 2) {                                                        \
            if (rank == 0) out[(size_t)bt * JD + tid] = v_;                    \
        } else {                                                               \
            Vreg += v_;                                                        \
            float vp_ = __shfl_down_sync(0xffffffffu, Vreg, 1);                \
            if (!(tid & 1)) Vh2[tid >> 1] = __floats2half2_rn(Vreg, vp_);      \
        }                                                                      \
    }                                                                          \
    __syncthreads();

    int bt = clust;
    for (int t = 0; bt < BATCH; t++, bt += NCLUST) {
        const unsigned int par = (unsigned int)(t & 1);
        float* sfA = (t & 1) ? sf1 : sf0;
        float* sfB = (t & 1) ? sf0 : sf1;
        float Vreg = 0.f;

        // ---- pass-0 (c = 0.1 uniform): consume chunks as they arrive ----
        {
            u64 a0 = 0ull, a1 = 0ull, a2 = 0ull, a3 = 0ull;
            int i = warp;
            mbar_wait(mbar_a, par);
            if (act) {
                for (; i < IQH; i += RW) {
                    uint4 u = *(const uint4*)(Usm + (size_t)i * NSLOT + sl);
                    add2(a0, h2_to_u64f2(*(__half2*)&u.x));
                    add2(a1, h2_to_u64f2(*(__half2*)&u.y));
                    add2(a2, h2_to_u64f2(*(__half2*)&u.z));
                    add2(a3, h2_to_u64f2(*(__half2*)&u.w));
                }
            }
            mbar_wait(mbar_a + 8, par);
            if (act) {
                for (; i < IQ; i += RW) {
                    uint4 u = *(const uint4*)(Usm + (size_t)i * NSLOT + sl);
                    add2(a0, h2_to_u64f2(*(__half2*)&u.x));
                    add2(a1, h2_to_u64f2(*(__half2*)&u.y));
                    add2(a2, h2_to_u64f2(*(__half2*)&u.z));
                    add2(a3, h2_to_u64f2(*(__half2*)&u.w));
                }
                F2U t0, t1, t2, t3;
                t0.u = a0; t1.u = a1; t2.u = a2; t3.u = a3;
                red2[warp * 80 + sl + 0] = t0.f;
                red2[warp * 80 + sl + 1] = t1.f;
                red2[warp * 80 + sl + 2] = t2.f;
                red2[warp * 80 + sl + 3] = t3.f;
            }
        }
        EPILOGUE(0, sfA, {})

        // ---- passes 1,2 from smem ----
        for (int p = 1; p <= 2; p++) {
            // ===== Stage A: fp16 dot t[i,j]; store e = exp(t) (fp16) =====
            {
                uint4 vr0 = make_uint4(0, 0, 0, 0), vr1 = vr0;
                if (actA) {
                    vr0 = *(const uint4*)(Vh2 + 8 * jA);
                    vr1 = *(const uint4*)(Vh2 + 8 * jA + 4);
                }
                __half2 w0 = *(__half2*)&vr0.x, w1 = *(__half2*)&vr0.y;
                __half2 w2 = *(__half2*)&vr0.z, w3 = *(__half2*)&vr0.w;
                __half2 w4 = *(__half2*)&vr1.x, w5 = *(__half2*)&vr1.y;
                __half2 w6 = *(__half2*)&vr1.z, w7 = *(__half2*)&vr1.w;
#pragma unroll 4
                for (int g = warp; g < IQ / 3; g += RW) {
                    const int i = g * 3 + ioA;
                    if (actA) {
                        const __half2* up = Usm + (size_t)i * NSLOT + 8 * jA;
                        uint4 u0 = *(const uint4*)up;
                        uint4 u1 = *(const uint4*)(up + 4);
                        __half2 acc = __hmul2(*(__half2*)&u0.x, w0);
                        acc = __hfma2(*(__half2*)&u0.y, w1, acc);
                        acc = __hfma2(*(__half2*)&u0.z, w2, acc);
                        acc = __hfma2(*(__half2*)&u0.w, w3, acc);
                        acc = __hfma2(*(__half2*)&u1.x, w4, acc);
                        acc = __hfma2(*(__half2*)&u1.y, w5, acc);
                        acc = __hfma2(*(__half2*)&u1.z, w6, acc);
                        acc = __hfma2(*(__half2*)&u1.w, w7, acc);
                        float2 tf = __half22float2(acc);
                        float e = __expf(tf.x + tf.y);  // |t| small
                        eh[i * NC + jA] = __float2half_rn(e);
                    }
                }
            }
            __syncthreads();

            // ===== Stage B: w[i] = 1 / sum_j e[i,j] =====
            if (tid < IQ) {
                const __half2* ep = (const __half2*)(eh + tid * NC);
                float s = 0.f;
#pragma unroll
                for (int q = 0; q < 5; q++) {
                    float2 f = __half22float2(ep[q]);
                    s += f.x + f.y;
                }
                wsm[tid] = __fdividef(1.f, s);
            }
            __syncthreads();

            // ===== Stage C: s += (e[i,j]*w[i]) * u[i,slot] =====
            u64 s0 = 0ull, s1 = 0ull, s2 = 0ull, s3 = 0ull;
#pragma unroll 4
            for (int i = warp; i < IQ; i += RW) {
                uint4 u = *(const uint4*)(Usm + (size_t)i * NSLOT + sl);
                float cf = __half2float(eh[i * NC + jC]) * wsm[i];
                u64 cc = pack2(cf, cf);
                fma2(s0, h2_to_u64f2(*(__half2*)&u.x), cc);
                fma2(s1, h2_to_u64f2(*(__half2*)&u.y), cc);
                fma2(s2, h2_to_u64f2(*(__half2*)&u.z), cc);
                fma2(s3, h2_to_u64f2(*(__half2*)&u.w), cc);
            }
            if (act) {
                F2U t0, t1, t2, t3;
                t0.u = s0; t1.u = s1; t2.u = s2; t3.u = s3;
                red2[warp * 80 + sl + 0] = t0.f;
                red2[warp * 80 + sl + 1] = t1.f;
                red2[warp * 80 + sl + 2] = t2.f;
                red2[warp * 80 + sl + 3] = t3.f;
            }
            if (p == 1) {
                EPILOGUE(1, sfB, {})
            } else {
                // prefetch next batch's slice once all Usm reads are done
                EPILOGUE(2, sfA, {
                    if (tid == 0 && bt + NCLUST < BATCH)
                        issue_tma(bt + NCLUST, rank, usm_a, mbar_a);
                })
            }
        }
    }

    cluster_sync();  // exit safety: peers may still read this CTA's sfin
}

// ---------------------------------------------------------------------------
extern "C" void kernel_launch(void* const* d_in, const int* in_sizes, int n_in,
                              void* d_out, int out_size) {
    const float* inputs = (const float*)d_in[0];  // [512, 1152, 8]
    const float* W = (const float*)d_in[1];       // [10, 1152, 16, 8]
    float* out = (float*)d_out;                   // [512, 10, 16]

    uhat_kernel<<<INC, 256>>>(inputs, W);

    const int smem = UBYTES + RW * JD * 4 + 2 * JD * 4 + NSLOT * 4 +
                     IQ * NC * 2 + IQ * 4 + 16;  // ~74 KB
    cudaFuncSetAttribute(route_kernel,
                         cudaFuncAttributeMaxDynamicSharedMemorySize, smem);
    route_kernel<<<NCLUST * CSZ, RTHR, smem>>>(out);
}

// round 17
// speedup vs baseline: 1.2719x; 1.1525x over previous
#include <cuda_runtime.h>
#include <cuda_fp16.h>
#include <cstdint>

#define BATCH 512
#define INC   1152
#define NC    10
#define DC    16
#define JD    160      // NC*DC
#define NSLOT 80       // half2 slots per (b,i): slot m holds jd {2m, 2m+1}
#define CSZ   6        // cluster CTAs per batch
#define IQ    192      // i-range per route CTA (INC / CSZ)
#define IQH   96       // TMA chunk split
#define RW    10       // warps per route CTA (320 threads)
#define RTHR  320
#define EPSQ  1e-7f
#define UBYTES (IQ * NSLOT * 4)    // 61440 B per CTA slice
#define CHBYTES (IQH * NSLOT * 4)  // 30720 B per TMA chunk

typedef unsigned long long u64;

// u_hat in fp16, layout [b][i][slot], slot m = jd pair (2m, 2m+1). 188 MB.
__device__ __half2 g_uhat[(size_t)BATCH * INC * NSLOT];

// ---------------------------------------------------------------------------
// helpers
// ---------------------------------------------------------------------------
__device__ __forceinline__ void cluster_sync() {
    asm volatile("barrier.cluster.arrive.aligned;\n\t"
                 "barrier.cluster.wait.aligned;" ::: "memory");
}

__device__ __forceinline__ float peer_f32(const float* p, unsigned int peer) {
    unsigned int a = (unsigned int)__cvta_generic_to_shared(p);
    unsigned int r;
    asm("mapa.shared::cluster.u32 %0, %1, %2;" : "=r"(r) : "r"(a), "r"(peer));
    float v;
    asm volatile("ld.shared::cluster.f32 %0, [%1];" : "=f"(v) : "r"(r));
    return v;
}

__device__ __forceinline__ u64 pack2(float lo, float hi) {
    u64 r;
    asm("mov.b64 %0, {%1, %2};" : "=l"(r) : "f"(lo), "f"(hi));
    return r;
}
__device__ __forceinline__ void fma2(u64& d, u64 a, u64 b) {
    asm("fma.rn.f32x2 %0, %1, %2, %3;" : "=l"(d) : "l"(a), "l"(b), "l"(d));
}
__device__ __forceinline__ void add2(u64& d, u64 a) {
    asm("add.rn.f32x2 %0, %0, %1;" : "+l"(d) : "l"(a));
}
// f32x2 {lo,hi} -> half2 {.x=lo, .y=hi}
__device__ __forceinline__ __half2 f2_to_h2(u64 v) {
    float lo, hi;
    asm("mov.b64 {%0, %1}, %2;" : "=f"(lo), "=f"(hi) : "l"(v));
    unsigned int r;
    asm("cvt.rn.f16x2.f32 %0, %1, %2;" : "=r"(r) : "f"(hi), "f"(lo));
    return *(__half2*)&r;
}
union F2U { float2 f; u64 u; };

__device__ __forceinline__ u64 h2_to_u64f2(__half2 h) {
    F2U t;
    t.f = __half22float2(h);
    return t.u;
}

__device__ __forceinline__ void mbar_wait0(unsigned int addr) {
    unsigned int done;
    asm volatile(
        "{\n\t.reg .pred p;\n\t"
        "mbarrier.try_wait.parity.acquire.cta.shared::cta.b64 p, [%1], %2;\n\t"
        "selp.b32 %0, 1, 0, p;\n\t}"
        : "=r"(done) : "r"(addr), "r"(0u) : "memory");
    while (!done) {
        asm volatile(
            "{\n\t.reg .pred p;\n\t"
            "mbarrier.try_wait.parity.acquire.cta.shared::cta.b64 p, [%1], %2, 0x989680;\n\t"
            "selp.b32 %0, 1, 0, p;\n\t}"
            : "=r"(done) : "r"(addr), "r"(0u) : "memory");
    }
}

// ---------------------------------------------------------------------------
// Kernel A: u_hat[b,i,jd] = sum_k inputs[b,i,k] * W[jd(i),k], fp16 output.
// R10 exact (48 us): one CTA per i; float4 inputs staged in smem; main loop
// is broadcast LDS.128 x2 + in-loop packs + FFMA2 + STG, unroll 2.
// ---------------------------------------------------------------------------
__global__ __launch_bounds__(256) void uhat_kernel(const float* __restrict__ inp,
                                                   const float* __restrict__ W) {
    __shared__ float4 sin[BATCH][2];   // 16 KB: inputs[b][i][0..7]

    const int tid = threadIdx.x;
    const int warp = tid >> 5;
    const int lane = tid & 31;
    const int i = blockIdx.x;

    // ---- stage inputs: thread t loads b = t, t+256 (2x2 LDG.128, MLP 4) ----
    {
        const float4* p0 = (const float4*)(inp + ((size_t)tid * INC + i) * 8);
        const float4* p1 =
            (const float4*)(inp + ((size_t)(tid + 256) * INC + i) * 8);
        float4 a0 = __ldg(p0), a1 = __ldg(p0 + 1);
        float4 b0 = __ldg(p1), b1 = __ldg(p1 + 1);
        sin[tid][0] = a0;
        sin[tid][1] = a1;
        sin[tid + 256][0] = b0;
        sin[tid + 256][1] = b1;
    }

    // ---- W pairs packed as f32x2 in registers ----
    u64 wpA[8], wpB[8], wpC[8];
#define LOADW(dst, jd0)                                                        \
    {                                                                          \
        const int j_ = (jd0) >> 4, d_ = (jd0) & 15;                            \
        const float4* p_ =                                                     \
            (const float4*)(W + (((size_t)j_ * INC + i) * DC + d_) * 8);       \
        float4 q0 = __ldg(p_), q1 = __ldg(p_ + 1), q2 = __ldg(p_ + 2),         \
               q3 = __ldg(p_ + 3);                                             \
        dst[0] = pack2(q0.x, q2.x); dst[1] = pack2(q0.y, q2.y);                \
        dst[2] = pack2(q0.z, q2.z); dst[3] = pack2(q0.w, q2.w);                \
        dst[4] = pack2(q1.x, q3.x); dst[5] = pack2(q1.y, q3.y);                \
        dst[6] = pack2(q1.z, q3.z); dst[7] = pack2(q1.w, q3.w);                \
    }
    LOADW(wpA, 2 * lane);
    LOADW(wpB, 64 + 2 * lane);
    if (lane < 16) {
        LOADW(wpC, 128 + 2 * lane);
    } else {
#pragma unroll
        for (int k = 0; k < 8; k++) wpC[k] = 0ull;
    }
#undef LOADW

    __syncthreads();

    // ---- main loop: warp owns 64 batches; inputs via broadcast LDS ----
    const int b0 = warp * 64;
#pragma unroll 2
    for (int bb = 0; bb < 64; bb++) {
        const int b = b0 + bb;
        float4 x = sin[b][0], y = sin[b][1];

        u64 in2[8];
        in2[0] = pack2(x.x, x.x); in2[1] = pack2(x.y, x.y);
        in2[2] = pack2(x.z, x.z); in2[3] = pack2(x.w, x.w);
        in2[4] = pack2(y.x, y.x); in2[5] = pack2(y.y, y.y);
        in2[6] = pack2(y.z, y.z); in2[7] = pack2(y.w, y.w);

        u64 aA = 0ull, aB = 0ull, aC = 0ull;
#pragma unroll
        for (int k = 0; k < 8; k++) {
            fma2(aA, in2[k], wpA[k]);
            fma2(aB, in2[k], wpB[k]);
            fma2(aC, in2[k], wpC[k]);
        }
        __half2* up = g_uhat + ((size_t)b * INC + i) * NSLOT;
        up[lane] = f2_to_h2(aA);
        up[32 + lane] = f2_to_h2(aB);
        if (lane < 16) up[64 + lane] = f2_to_h2(aC);
    }
}

// ---------------------------------------------------------------------------
// Kernel R: routing. Cluster of 6 CTAs per batch (IQ=192, 320 threads,
// ~74 KB smem -> 3 CTAs/SM). 2-chunk cp.async.bulk overlapped with pass-0.
// NEW: pass-0 and stage C use ALL 32 lanes via virtual-lane remap --
// p = (warp%5)*32+lane covers 8 i-rows x 20 chunks per 5-warp group; each
// thread keeps a fixed chunk c=p%20 (accumulator slot-pinned); lanes l and
// l+20 share a chunk and fold via one shfl_down(20) at loop end; lanes 0..19
// write the SAME red layout as before (epilogue unchanged).
// ---------------------------------------------------------------------------
__global__ __launch_bounds__(RTHR, 3) __cluster_dims__(CSZ, 1, 1)
void route_kernel(float* __restrict__ out) {
    extern __shared__ char smraw[];
    __half2* Usm = (__half2*)smraw;                            // 61440 B
    float* red = (float*)(smraw + UBYTES);                     // RW*160 f
    float* sf0 = red + RW * JD;                                // 160 (DSMEM)
    float* sf1 = sf0 + JD;                                     // 160 (DSMEM)
    __half2* Vh2 = (__half2*)(sf1 + JD);                       // 80 half2
    __half* eh = (__half*)(Vh2 + NSLOT);                       // IQ*10 half
    float* wsm = (float*)(eh + IQ * NC);                       // IQ floats
    u64* mbar = (u64*)(wsm + IQ);                              // 2 mbarriers

    const int tid = threadIdx.x;
    const int warp = tid >> 5;
    const int lane = tid & 31;
    const int b = blockIdx.x / CSZ;
    const unsigned int rank = blockIdx.x % CSZ;
    float2* red2 = (float2*)red;
    const unsigned int mbar_a = (unsigned int)__cvta_generic_to_shared(mbar);
    const unsigned int usm_a = (unsigned int)__cvta_generic_to_shared(Usm);

    // virtual-lane mapping for pass-0 / stage C (all 32 lanes active)
    const int p = (warp % 5) * 32 + lane;  // 0..159 within 5-warp group
    const int grp = warp / 5;              // 0 or 1
    const int ioff = p / 20;               // 0..7
    const int cch = p - 20 * ioff;         // fixed chunk 0..19
    const int slc = 4 * cch;               // half2-uint4 index within row
    const int i0 = grp * 8 + ioff;         // i advances by 16 per iteration
    const int jV = cch >> 1;               // j for this chunk (8c..8c+7 jd)

    float Vreg = 0.f;  // running V for this thread's jd (tid < 160)

    // ---- 2-chunk bulk async copy: g_uhat slice -> smem ----
    if (tid == 0) {
        asm volatile("mbarrier.init.shared.b64 [%0], %1;" ::"r"(mbar_a),
                     "r"(1u) : "memory");
        asm volatile("mbarrier.init.shared.b64 [%0], %1;" ::"r"(mbar_a + 8),
                     "r"(1u) : "memory");
    }
    __syncthreads();
    if (tid == 0) {
        const __half2* gsrc = g_uhat + ((size_t)b * INC + rank * IQ) * NSLOT;
#pragma unroll
        for (int c = 0; c < 2; c++) {
            asm volatile(
                "mbarrier.arrive.expect_tx.shared.b64 _, [%0], %1;"
                ::"r"(mbar_a + 8 * c), "r"((unsigned int)CHBYTES) : "memory");
            asm volatile(
                "cp.async.bulk.shared::cta.global.mbarrier::complete_tx::bytes "
                "[%0], [%1], %2, [%3];"
                ::"r"(usm_a + c * CHBYTES),
                "l"((const void*)(gsrc + (size_t)c * IQH * NSLOT)),
                "r"((unsigned int)CHBYTES), "r"(mbar_a + 8 * c) : "memory");
        }
    }

    // fold (lane, lane+20) partners sharing a chunk, write red (lanes 0..19)
#define REDUCE_WRITE(A0, A1, A2, A3)                                           \
    {                                                                          \
        F2U t0_, t1_, t2_, t3_;                                                \
        t0_.u = (A0); t1_.u = (A1); t2_.u = (A2); t3_.u = (A3);                \
        float v_[8] = {t0_.f.x, t0_.f.y, t1_.f.x, t1_.f.y,                     \
                       t2_.f.x, t2_.f.y, t3_.f.x, t3_.f.y};                    \
        _Pragma("unroll") for (int q_ = 0; q_ < 8; q_++) {                     \
            float o_ = __shfl_down_sync(0xffffffffu, v_[q_], 20);              \
            if (lane < 12) v_[q_] += o_;                                       \
        }                                                                      \
        if (lane < 20) {                                                       \
            red2[warp * 80 + slc + 0] = make_float2(v_[0], v_[1]);             \
            red2[warp * 80 + slc + 1] = make_float2(v_[2], v_[3]);             \
            red2[warp * 80 + slc + 2] = make_float2(v_[4], v_[5]);             \
            red2[warp * 80 + slc + 3] = make_float2(v_[6], v_[7]);             \
        }                                                                      \
    }

    // ---- pass-0 (c = 0.1 uniform): consume chunks as they arrive ----
    {
        u64 a0 = 0ull, a1 = 0ull, a2 = 0ull, a3 = 0ull;
        int it = 0;
        mbar_wait0(mbar_a);
#pragma unroll 3
        for (; it < 6; it++) {  // i in [0, 96)
            const int i = i0 + it * 16;
            uint4 u = *(const uint4*)(Usm + (size_t)i * NSLOT + slc);
            add2(a0, h2_to_u64f2(*(__half2*)&u.x));
            add2(a1, h2_to_u64f2(*(__half2*)&u.y));
            add2(a2, h2_to_u64f2(*(__half2*)&u.z));
            add2(a3, h2_to_u64f2(*(__half2*)&u.w));
        }
        mbar_wait0(mbar_a + 8);
#pragma unroll 3
        for (; it < 12; it++) {  // i in [96, 192)
            const int i = i0 + it * 16;
            uint4 u = *(const uint4*)(Usm + (size_t)i * NSLOT + slc);
            add2(a0, h2_to_u64f2(*(__half2*)&u.x));
            add2(a1, h2_to_u64f2(*(__half2*)&u.y));
            add2(a2, h2_to_u64f2(*(__half2*)&u.z));
            add2(a3, h2_to_u64f2(*(__half2*)&u.w));
        }
        REDUCE_WRITE(a0, a1, a2, a3)
    }

    // lane mapping for stage A: lane = io*10 + j, io in 0..2, j in 0..9
    const int ioA = lane / 10;
    const int jA = lane - 10 * ioA;
    const bool actA = (lane < 30);

    // ---- per-pass epilogue (p = 0,1,2), sfbuf double-buffered ----
#define EPILOGUE(P, SF)                                                        \
    __syncthreads();                                                           \
    if (tid < JD) {                                                            \
        float s_ = 0.f;                                                        \
        _Pragma("unroll") for (int w_ = 0; w_ < RW; w_++)                      \
            s_ += red[w_ * JD + tid];                                          \
        (SF)[tid] = s_;                                                        \
    }                                                                          \
    cluster_sync();                                                            \
    if (tid < JD) {                                                            \
        float s_ = (SF)[tid];                                                  \
        _Pragma("unroll") for (unsigned int r_ = 1; r_ < CSZ; r_++) {          \
            unsigned int pr_ = rank + r_;                                      \
            if (pr_ >= CSZ) pr_ -= CSZ;                                        \
            s_ += peer_f32((SF) + tid, pr_);                                   \
        }                                                                      \
        if ((P) == 0) s_ *= 0.1f;                                              \
        float sq_ = s_ * s_;                                                   \
        sq_ += __shfl_xor_sync(0xffffffffu, sq_, 1);                           \
        sq_ += __shfl_xor_sync(0xffffffffu, sq_, 2);                           \
        sq_ += __shfl_xor_sync(0xffffffffu, sq_, 4);                           \
        sq_ += __shfl_xor_sync(0xffffffffu, sq_, 8);                           \
        float scl_ = sq_ / ((1.0f + sq_) * sqrtf(sq_ + EPSQ));                 \
        float v_ = scl_ * s_;                                                  \
        if ((P) == 2) {                                                        \
            if (rank == 0) out[(size_t)b * JD + tid] = v_;                     \
        } else {                                                               \
            Vreg += v_;                                                        \
            float vp_ = __shfl_down_sync(0xffffffffu, Vreg, 1);                \
            if (!(tid & 1)) Vh2[tid >> 1] = __floats2half2_rn(Vreg, vp_);      \
        }                                                                      \
    }                                                                          \
    __syncthreads();

    EPILOGUE(0, sf0)

    // ---- passes 1,2 from smem ----
    for (int pp = 1; pp <= 2; pp++) {
        // ===== Stage A: fp16 dot t[i,j]; store e = exp(t) (fp16) =====
        {
            uint4 vr0 = make_uint4(0, 0, 0, 0), vr1 = vr0;
            if (actA) {
                vr0 = *(const uint4*)(Vh2 + 8 * jA);
                vr1 = *(const uint4*)(Vh2 + 8 * jA + 4);
            }
            __half2 w0 = *(__half2*)&vr0.x, w1 = *(__half2*)&vr0.y;
            __half2 w2 = *(__half2*)&vr0.z, w3 = *(__half2*)&vr0.w;
            __half2 w4 = *(__half2*)&vr1.x, w5 = *(__half2*)&vr1.y;
            __half2 w6 = *(__half2*)&vr1.z, w7 = *(__half2*)&vr1.w;
#pragma unroll 4
            for (int g = warp; g < IQ / 3; g += RW) {
                const int i = g * 3 + ioA;
                if (actA) {
                    const __half2* up = Usm + (size_t)i * NSLOT + 8 * jA;
                    uint4 u0 = *(const uint4*)up;
                    uint4 u1 = *(const uint4*)(up + 4);
                    __half2 acc = __hmul2(*(__half2*)&u0.x, w0);
                    acc = __hfma2(*(__half2*)&u0.y, w1, acc);
                    acc = __hfma2(*(__half2*)&u0.z, w2, acc);
                    acc = __hfma2(*(__half2*)&u0.w, w3, acc);
                    acc = __hfma2(*(__half2*)&u1.x, w4, acc);
                    acc = __hfma2(*(__half2*)&u1.y, w5, acc);
                    acc = __hfma2(*(__half2*)&u1.z, w6, acc);
                    acc = __hfma2(*(__half2*)&u1.w, w7, acc);
                    float2 tf = __half22float2(acc);
                    float e = __expf(tf.x + tf.y);  // |t| small: no max-sub
                    eh[i * NC + jA] = __float2half_rn(e);
                }
            }
        }
        __syncthreads();

        // ===== Stage B: w[i] = 1 / sum_j e[i,j] =====
        if (tid < IQ) {
            const __half2* ep = (const __half2*)(eh + tid * NC);
            float s = 0.f;
#pragma unroll
            for (int q = 0; q < 5; q++) {
                float2 f = __half22float2(ep[q]);
                s += f.x + f.y;
            }
            wsm[tid] = __fdividef(1.f, s);
        }
        __syncthreads();

        // ===== Stage C: s += (e[i,j]*w[i]) * u[i,chunk], all 32 lanes =====
        {
            u64 s0 = 0ull, s1 = 0ull, s2 = 0ull, s3 = 0ull;
#pragma unroll 4
            for (int it = 0; it < 12; it++) {
                const int i = i0 + it * 16;
                uint4 u = *(const uint4*)(Usm + (size_t)i * NSLOT + slc);
                float cf = __half2float(eh[i * NC + jV]) * wsm[i];
                u64 cc = pack2(cf, cf);
                fma2(s0, h2_to_u64f2(*(__half2*)&u.x), cc);
                fma2(s1, h2_to_u64f2(*(__half2*)&u.y), cc);
                fma2(s2, h2_to_u64f2(*(__half2*)&u.z), cc);
                fma2(s3, h2_to_u64f2(*(__half2*)&u.w), cc);
            }
            REDUCE_WRITE(s0, s1, s2, s3)
        }
        if (pp == 1) {
            EPILOGUE(1, sf1)
        } else {
            EPILOGUE(2, sf0)
        }
    }

    cluster_sync();  // exit safety: peers may still read this CTA's sfin
}

// ---------------------------------------------------------------------------
extern "C" void kernel_launch(void* const* d_in, const int* in_sizes, int n_in,
                              void* d_out, int out_size) {
    const float* inputs = (const float*)d_in[0];  // [512, 1152, 8]
    const float* W = (const float*)d_in[1];       // [10, 1152, 16, 8]
    float* out = (float*)d_out;                   // [512, 10, 16]

    uhat_kernel<<<INC, 256>>>(inputs, W);

    const int smem = UBYTES + RW * JD * 4 + 2 * JD * 4 + NSLOT * 4 +
                     IQ * NC * 2 + IQ * 4 + 16;  // ~74 KB
    cudaFuncSetAttribute(route_kernel,
                         cudaFuncAttributeMaxDynamicSharedMemorySize, smem);
    route_kernel<<<BATCH * CSZ, RTHR, smem>>>(out);
}